// round 4
// baseline (speedup 1.0000x reference)
#include <cuda_runtime.h>
#include <cstdint>
#include <cstddef>

// Correlation: out[b, ix*21+iy, h, w] = sum_c f1[b,c,h,w] * f2[b,c,h+2ix-20, w+2iy-20]
// B=4, C=128, H=96, W=192, D=20, stride 2.
//
// Packed-parity: outputs (w=2u, 2u+1) read f2 pairs (2v, 2v+1), v=u+iy-10 ->
// one fma.rn.f32x2 per tap does both parities. cp.async staging, double buffer.
// Thread owns 8 w (4 pair slots) x 11 taps = 44 packed accumulators.
// Layout uses the standard bijective 128B XOR swizzle (16B granules within
// each 128B block) -> conflict-free LDS.128 phases, collision-free stores.

#define NTHR   336                   // 7 q * 2 jh * 24 t
#define CC     4                     // channels per chunk
#define ROWF1  192                   // f1 row floats (768B = 6x128B)
#define ROWF2  256                   // f2 row floats (1024B; 116 pair slots used)
#define ROWC   (ROWF1 + 7*ROWF2)     // 1984 floats per channel (7936B, 128B mult)
#define BUFF   (CC*ROWC)             // 7936 floats per buffer (31744B)
#define NSEG   (CC*8*48)             // 1536 x 16B segments per chunk
#define NITER_SEG 5                  // ceil(1536/336)

typedef unsigned long long ull;

// Standard 128B swizzle: XOR 16B-granule bits [6:4] with 128B-row bits [9:7].
// Bijective on any 128B-aligned region; preserves 16B granularity.
__device__ __forceinline__ uint32_t sw128(uint32_t byte_off) {
    return byte_off ^ ((byte_off >> 3) & 0x70u);
}

__device__ __forceinline__ ull ffma2(ull a, ull b, ull c) {
    ull d;
    asm("fma.rn.f32x2 %0, %1, %2, %3;" : "=l"(d) : "l"(a), "l"(b), "l"(c));
    return d;
}

__device__ __forceinline__ void cp16(uint32_t dst_smem, const float* src) {
    asm volatile("cp.async.cg.shared.global [%0], [%1], 16;" :: "r"(dst_smem), "l"(src));
}

__global__ void __launch_bounds__(NTHR, 1)
corr_kernel(const float* __restrict__ f1, const float* __restrict__ f2,
            float* __restrict__ out)
{
    extern __shared__ __align__(128) float smem[];
    const int h   = blockIdx.x;   // 0..95
    const int b   = blockIdx.y;   // 0..3
    const int ixg = blockIdx.z;   // 0..2
    const int tid = threadIdx.x;

    const int q  = tid / 48;      // 0..6 : ix within group
    const int r  = tid % 48;
    const int jh = r / 24;        // 0..1 : tap half (j = 10*jh + jj)
    const int t  = r % 24;        // u-tile
    const int u0 = 4 * t;         // first pair slot owned (w = 8t .. 8t+7)
    const int m0 = 10 * jh;
    const int h2base = h + 14 * ixg - 20;

    // Zero both buffers once: covers edge pads and OOB rows (positions fixed,
    // channel-independent). Valid interiors overwritten by cp.async each chunk.
    for (int i = tid; i < 2 * BUFF; i += NTHR) smem[i] = 0.0f;
    __syncthreads();

    const uint32_t sbase = (uint32_t)__cvta_generic_to_shared(smem);

    auto issue_chunk = [&](int c0, int bufsel) {
        uint32_t dbase = sbase + (uint32_t)bufsel * (BUFF * 4);
        #pragma unroll
        for (int i = 0; i < NITER_SEG; i++) {
            int idx = tid + i * NTHR;
            if (idx < NSEG) {
                int op = idx % 48;          // 16B segment within row
                int r8 = (idx / 48) % 8;    // 0 = f1 row, 1..7 = f2 rows
                int c  = idx / 384;
                if (r8 == 0) {
                    // f1 slot 2op at row-rel byte 16*op
                    const float* src = f1 + (((size_t)(b*128 + c0 + c))*96 + h)*192 + op*4;
                    cp16(dbase + (uint32_t)(c * ROWC * 4) + sw128((uint32_t)(op * 16)), src);
                } else {
                    int qq = r8 - 1;
                    int h2 = h2base + 2 * qq;
                    if ((unsigned)h2 < 96u) {
                        // f2 pair vp=2op stored at slot vp+10 -> byte 16*op + 80
                        const float* src = f2 + (((size_t)(b*128 + c0 + c))*96 + h2)*192 + op*4;
                        cp16(dbase + (uint32_t)((c*ROWC + ROWF1 + qq*ROWF2) * 4)
                                   + sw128((uint32_t)(op * 16 + 80)), src);
                    }
                }
            }
        }
        asm volatile("cp.async.commit_group;");
    };

    ull acc[44];                      // [k 0..3][jj 0..10] packed float2
    #pragma unroll
    for (int i = 0; i < 44; i++) acc[i] = 0ull;

    issue_chunk(0, 0);

    #pragma unroll 1
    for (int cc = 0; cc < 32; cc++) {
        if (cc + 1 < 32) {
            issue_chunk((cc + 1) * CC, (cc + 1) & 1);
            asm volatile("cp.async.wait_group 1;");
        } else {
            asm volatile("cp.async.wait_group 0;");
        }
        __syncthreads();

        const float* buf = smem + (cc & 1) * BUFF;
        #pragma unroll
        for (int c = 0; c < CC; c++) {
            const char* f1row = (const char*)(buf + c * ROWC);
            const char* wrow  = (const char*)(buf + c * ROWC + ROWF1 + q * ROWF2);

            ulonglong2 A0 = *(const ulonglong2*)(f1row + sw128((uint32_t)(u0 * 8)));
            ulonglong2 A1 = *(const ulonglong2*)(f1row + sw128((uint32_t)((u0 + 2) * 8)));
            ull a0 = A0.x, a1 = A0.y, a2 = A1.x, a3 = A1.y;

            #pragma unroll
            for (int i = 0; i < 7; i++) {
                // storage slots (u0+m0+2i, +1); slot s holds f2 pair vp = s-10.
                // acc[k][jj] needs slot u0+k+m0+jj  =>  jj = 2i-k (x), 2i+1-k (y).
                ulonglong2 wv = *(const ulonglong2*)(
                    wrow + sw128((uint32_t)((u0 + m0 + 2*i) * 8)));
                #pragma unroll
                for (int k = 0; k < 4; k++) {
                    ull av = (k == 0) ? a0 : (k == 1) ? a1 : (k == 2) ? a2 : a3;
                    int j0 = 2*i - k;
                    if (j0 >= 0 && j0 < 11)
                        acc[k*11 + j0] = ffma2(av, wv.x, acc[k*11 + j0]);
                    int j1 = 2*i + 1 - k;
                    if (j1 >= 0 && j1 < 11)
                        acc[k*11 + j1] = ffma2(av, wv.y, acc[k*11 + j1]);
                }
            }
        }
        __syncthreads();
    }

    // Store: j = m0 + jj (j=10 computed identically by both halves).
    const int ix = ixg * 7 + q;
    #pragma unroll
    for (int jj = 0; jj < 11; jj++) {
        int j = m0 + jj;
        size_t base = (((size_t)b * 441 + (size_t)ix * 21 + j) * 96 + h) * 192 + 8 * t;
        ulonglong2 s0, s1;
        s0.x = acc[0*11 + jj]; s0.y = acc[1*11 + jj];   // w = 8t..8t+3
        s1.x = acc[2*11 + jj]; s1.y = acc[3*11 + jj];   // w = 8t+4..8t+7
        *reinterpret_cast<ulonglong2*>(out + base)     = s0;
        *reinterpret_cast<ulonglong2*>(out + base + 4) = s1;
    }
}

extern "C" void kernel_launch(void* const* d_in, const int* in_sizes, int n_in,
                              void* d_out, int out_size)
{
    const float* f1 = (const float*)d_in[0];
    const float* f2 = (const float*)d_in[1];
    float* out = (float*)d_out;

    size_t smem_bytes = (size_t)2 * BUFF * sizeof(float);   // 63488 B
    cudaFuncSetAttribute(corr_kernel, cudaFuncAttributeMaxDynamicSharedMemorySize,
                         (int)smem_bytes);

    dim3 grid(96, 4, 3);   // (h, b, ix-group)
    corr_kernel<<<grid, NTHR, smem_bytes>>>(f1, f2, out);
}